// round 1
// baseline (speedup 1.0000x reference)
#include <cuda_runtime.h>
#include <math.h>
#include <stdint.h>

#define HID 2048
#define NTOK 4096          // B*S = 2*2048
#define SEQ 2048
#define NH 16
#define HD 128
#define KW 512             // HID/4 int8-packed words
#define BH 32              // B*NH
static __device__ __constant__ float SCALE_ATTN = 0.08838834764831845f; // 1/sqrt(128)

// ---------------- scratch (device globals; no allocation allowed) ----------------
__device__ int8_t g_wq[4][HID * HID];            // ternary weights
__device__ float  g_ws[4];                       // weight scales
__device__ double g_wred[4 * 1024];              // partial |w| sums
__device__ int8_t g_xq[NTOK * HID];              // int8 activations
__device__ float  g_gs[NTOK];                    // per-token absmax scale g (incl. +EPS)
__device__ float  g_q[NTOK * HID];
__device__ float  g_k[NTOK * HID];
__device__ float  g_v[NTOK * HID];
__device__ float  g_ctx[NTOK * HID];
__device__ float  g_cos[SEQ * 64];
__device__ float  g_sin[SEQ * 64];
__device__ float  g_scores[(size_t)BH * SEQ * SEQ];  // 512 MB

// ---------------- weight scale: deterministic two-pass mean(|w|) ----------------
__global__ __launch_bounds__(256) void wabs_partial(const float* __restrict__ w, int which) {
    __shared__ double sh[256];
    int base = blockIdx.x * 4096;
    double acc = 0.0;
    for (int i = threadIdx.x; i < 4096; i += 256) acc += (double)fabsf(w[base + i]);
    sh[threadIdx.x] = acc; __syncthreads();
    for (int st = 128; st > 0; st >>= 1) {
        if (threadIdx.x < st) sh[threadIdx.x] += sh[threadIdx.x + st];
        __syncthreads();
    }
    if (threadIdx.x == 0) g_wred[which * 1024 + blockIdx.x] = sh[0];
}

__global__ __launch_bounds__(256) void wabs_final(int which) {
    __shared__ double sh[256];
    double acc = 0.0;
    for (int i = threadIdx.x; i < 1024; i += 256) acc += g_wred[which * 1024 + i];
    sh[threadIdx.x] = acc; __syncthreads();
    for (int st = 128; st > 0; st >>= 1) {
        if (threadIdx.x < st) sh[threadIdx.x] += sh[threadIdx.x + st];
        __syncthreads();
    }
    if (threadIdx.x == 0)
        g_ws[which] = (float)(sh[0] / (double)(HID * HID)) + 1e-5f;
}

__global__ __launch_bounds__(256) void quant_w(const float* __restrict__ w, int which) {
    float s = g_ws[which];
    int base = blockIdx.x * 1024;
    #pragma unroll
    for (int k = 0; k < 4; k++) {
        int i = base + threadIdx.x + k * 256;
        float t = rintf(w[i] / s);
        t = fminf(fmaxf(t, -1.0f), 1.0f);
        g_wq[which][i] = (int8_t)t;
    }
}

// ---------------- activation quant: per-token absmax int8 ----------------
__global__ __launch_bounds__(256) void quant_act(const float* __restrict__ xin, int use_ctx) {
    __shared__ float sh[256];
    int t = blockIdx.x;
    const float* x = use_ctx ? (const float*)g_ctx : xin;
    const float* row = x + (size_t)t * HID;
    float m = 0.0f;
    for (int i = threadIdx.x; i < HID; i += 256) m = fmaxf(m, fabsf(row[i]));
    sh[threadIdx.x] = m; __syncthreads();
    for (int st = 128; st > 0; st >>= 1) {
        if (threadIdx.x < st) sh[threadIdx.x] = fmaxf(sh[threadIdx.x], sh[threadIdx.x + st]);
        __syncthreads();
    }
    float g = sh[0] + 1e-5f;
    if (threadIdx.x == 0) g_gs[t] = g;
    float inv = 127.0f / g;
    for (int i = threadIdx.x; i < HID; i += 256) {
        float v = rintf(row[i] * inv);
        v = fminf(fmaxf(v, -127.0f), 127.0f);
        g_xq[(size_t)t * HID + i] = (int8_t)v;
    }
}

// ---------------- int8 dp4a GEMM: out[t,o] = (g_t*s/127) * sum_k xq*wq ----------------
// A: g_xq [4096][512 words], B: g_wq[which] [2048][512 words]
__global__ __launch_bounds__(256) void gemm_i8(int which, float* __restrict__ out_param, int dest) {
    __shared__ int As[128][17];
    __shared__ int Bs[128][17];
    const int* A = (const int*)g_xq;
    const int* B = (const int*)g_wq[which];
    float* out = (dest == 0) ? g_q : (dest == 1) ? g_k : (dest == 2) ? g_v : out_param;

    int row0 = blockIdx.y * 128, col0 = blockIdx.x * 128;
    int tid = threadIdx.x, ty = tid >> 4, tx = tid & 15;
    int acc[8][8];
    #pragma unroll
    for (int i = 0; i < 8; i++)
        #pragma unroll
        for (int j = 0; j < 8; j++) acc[i][j] = 0;

    for (int k0 = 0; k0 < KW; k0 += 16) {
        #pragma unroll
        for (int s = 0; s < 2; s++) {
            int idx = tid + s * 256;             // 0..511
            int r = idx >> 2, c4 = (idx & 3) * 4;
            int4 a = *(const int4*)&A[(size_t)(row0 + r) * KW + k0 + c4];
            As[r][c4] = a.x; As[r][c4 + 1] = a.y; As[r][c4 + 2] = a.z; As[r][c4 + 3] = a.w;
            int4 b = *(const int4*)&B[(size_t)(col0 + r) * KW + k0 + c4];
            Bs[r][c4] = b.x; Bs[r][c4 + 1] = b.y; Bs[r][c4 + 2] = b.z; Bs[r][c4 + 3] = b.w;
        }
        __syncthreads();
        #pragma unroll
        for (int kw = 0; kw < 16; kw++) {
            int af[8], bf[8];
            #pragma unroll
            for (int i = 0; i < 8; i++) af[i] = As[ty * 8 + i][kw];
            #pragma unroll
            for (int j = 0; j < 8; j++) bf[j] = Bs[tx + 16 * j][kw];
            #pragma unroll
            for (int i = 0; i < 8; i++)
                #pragma unroll
                for (int j = 0; j < 8; j++)
                    acc[i][j] = __dp4a(af[i], bf[j], acc[i][j]);
        }
        __syncthreads();
    }
    float s = g_ws[which];
    #pragma unroll
    for (int i = 0; i < 8; i++) {
        int r = row0 + ty * 8 + i;
        float mult = g_gs[r] * s * (1.0f / 127.0f);
        #pragma unroll
        for (int j = 0; j < 8; j++)
            out[(size_t)r * HID + col0 + tx + 16 * j] = (float)acc[i][j] * mult;
    }
}

// ---------------- RoPE table + apply ----------------
__global__ __launch_bounds__(256) void rope_table() {
    int idx = blockIdx.x * 256 + threadIdx.x;     // 131072 = 2048*64
    int pos = idx >> 6, j = idx & 63;
    double f = (double)pos * exp(-(double)j * (log(10000.0) / 64.0));
    g_cos[idx] = (float)cos(f);
    g_sin[idx] = (float)sin(f);
}

__global__ __launch_bounds__(256) void rope_apply() {
    int t = blockIdx.x;                 // token 0..4095
    int pos = t & (SEQ - 1);
    float* q = g_q + (size_t)t * HID;
    float* k = g_k + (size_t)t * HID;
    for (int p = threadIdx.x; p < 1024; p += 256) {
        int h = p >> 6, j = p & 63;
        float c = g_cos[pos * 64 + j];
        float s = g_sin[pos * 64 + j];
        int f1 = h * 128 + j, f2 = f1 + 64;
        float a = q[f1], b = q[f2];
        q[f1] = a * c - b * s;
        q[f2] = b * c + a * s;
        float ak = k[f1], bk = k[f2];
        k[f1] = ak * c - bk * s;
        k[f2] = bk * c + ak * s;
    }
}

// ---------------- QK^T: scores[bh][i][j] = scale * sum_d q*k ----------------
__global__ __launch_bounds__(256) void qk_gemm() {
    __shared__ float Qs[128][33];
    __shared__ float Ks[128][33];
    int bh = blockIdx.z, b = bh >> 4, h = bh & 15;
    const float* qb = g_q + (size_t)b * SEQ * HID + h * HD;
    const float* kb = g_k + (size_t)b * SEQ * HID + h * HD;
    int i0 = blockIdx.y * 128, j0 = blockIdx.x * 128;
    int tid = threadIdx.x, ty = tid >> 4, tx = tid & 15;
    float acc[8][8];
    #pragma unroll
    for (int i = 0; i < 8; i++)
        #pragma unroll
        for (int j = 0; j < 8; j++) acc[i][j] = 0.0f;

    for (int d0 = 0; d0 < HD; d0 += 32) {
        #pragma unroll
        for (int s = 0; s < 4; s++) {
            int idx = tid + s * 256;              // 0..1023
            int r = idx >> 3, c = (idx & 7) * 4;
            float4 vq = *(const float4*)&qb[(size_t)(i0 + r) * HID + d0 + c];
            Qs[r][c] = vq.x; Qs[r][c + 1] = vq.y; Qs[r][c + 2] = vq.z; Qs[r][c + 3] = vq.w;
            float4 vk = *(const float4*)&kb[(size_t)(j0 + r) * HID + d0 + c];
            Ks[r][c] = vk.x; Ks[r][c + 1] = vk.y; Ks[r][c + 2] = vk.z; Ks[r][c + 3] = vk.w;
        }
        __syncthreads();
        #pragma unroll
        for (int kk = 0; kk < 32; kk++) {
            float af[8], bf[8];
            #pragma unroll
            for (int i = 0; i < 8; i++) af[i] = Qs[ty * 8 + i][kk];
            #pragma unroll
            for (int j = 0; j < 8; j++) bf[j] = Ks[tx + 16 * j][kk];
            #pragma unroll
            for (int i = 0; i < 8; i++)
                #pragma unroll
                for (int j = 0; j < 8; j++)
                    acc[i][j] += af[i] * bf[j];
        }
        __syncthreads();
    }
    #pragma unroll
    for (int i = 0; i < 8; i++) {
        size_t rbase = ((size_t)bh * SEQ + i0 + ty * 8 + i) * SEQ + j0;
        #pragma unroll
        for (int j = 0; j < 8; j++)
            g_scores[rbase + tx + 16 * j] = acc[i][j] * SCALE_ATTN;
    }
}

// ---------------- row softmax over 2048 ----------------
__global__ __launch_bounds__(256) void softmax_kernel() {
    __shared__ float sh[256];
    size_t row = blockIdx.x;
    float* p = g_scores + row * SEQ;
    int tid = threadIdx.x;
    float v[8];
    float m = -INFINITY;
    #pragma unroll
    for (int i = 0; i < 8; i++) { v[i] = p[tid + i * 256]; m = fmaxf(m, v[i]); }
    sh[tid] = m; __syncthreads();
    for (int st = 128; st > 0; st >>= 1) {
        if (tid < st) sh[tid] = fmaxf(sh[tid], sh[tid + st]);
        __syncthreads();
    }
    m = sh[0]; __syncthreads();
    float s = 0.0f;
    #pragma unroll
    for (int i = 0; i < 8; i++) { v[i] = expf(v[i] - m); s += v[i]; }
    sh[tid] = s; __syncthreads();
    for (int st = 128; st > 0; st >>= 1) {
        if (tid < st) sh[tid] += sh[tid + st];
        __syncthreads();
    }
    float inv = 1.0f / sh[0];
    #pragma unroll
    for (int i = 0; i < 8; i++) p[tid + i * 256] = v[i] * inv;
}

// ---------------- P·V: ctx[b, i, h*128+d] = sum_j P[bh,i,j] V[bh,j,d] ----------------
__global__ __launch_bounds__(256) void pv_gemm() {
    __shared__ float Ps[128][33];
    __shared__ float Vs[32][132];
    int bh = blockIdx.y, b = bh >> 4, h = bh & 15;
    const float* vb = g_v + (size_t)b * SEQ * HID + h * HD;
    int i0 = blockIdx.x * 128;
    int tid = threadIdx.x, ty = tid >> 4, tx = tid & 15;
    float acc[8][8];
    #pragma unroll
    for (int i = 0; i < 8; i++)
        #pragma unroll
        for (int j = 0; j < 8; j++) acc[i][j] = 0.0f;

    for (int kb = 0; kb < SEQ; kb += 32) {
        #pragma unroll
        for (int s = 0; s < 4; s++) {
            int idx = tid + s * 256;              // 0..1023
            int rp = idx >> 3, cp = (idx & 7) * 4;
            float4 vp = *(const float4*)&g_scores[((size_t)bh * SEQ + i0 + rp) * SEQ + kb + cp];
            Ps[rp][cp] = vp.x; Ps[rp][cp + 1] = vp.y; Ps[rp][cp + 2] = vp.z; Ps[rp][cp + 3] = vp.w;
            int rv = idx >> 5, cv = (idx & 31) * 4;
            float4 vv = *(const float4*)&vb[(size_t)(kb + rv) * HID + cv];
            Vs[rv][cv] = vv.x; Vs[rv][cv + 1] = vv.y; Vs[rv][cv + 2] = vv.z; Vs[rv][cv + 3] = vv.w;
        }
        __syncthreads();
        #pragma unroll
        for (int kk = 0; kk < 32; kk++) {
            float pf[8], vf[8];
            #pragma unroll
            for (int i = 0; i < 8; i++) pf[i] = Ps[ty * 8 + i][kk];
            #pragma unroll
            for (int j = 0; j < 8; j++) vf[j] = Vs[kk][tx + 16 * j];
            #pragma unroll
            for (int i = 0; i < 8; i++)
                #pragma unroll
                for (int j = 0; j < 8; j++)
                    acc[i][j] += pf[i] * vf[j];
        }
        __syncthreads();
    }
    #pragma unroll
    for (int i = 0; i < 8; i++) {
        size_t rbase = ((size_t)(b * SEQ + i0 + ty * 8 + i)) * HID + h * HD;
        #pragma unroll
        for (int j = 0; j < 8; j++)
            g_ctx[rbase + tx + 16 * j] = acc[i][j];
    }
}

// ---------------- launcher ----------------
extern "C" void kernel_launch(void* const* d_in, const int* in_sizes, int n_in,
                              void* d_out, int out_size) {
    const float* x = (const float*)d_in[0];
    const float* w[4] = { (const float*)d_in[1], (const float*)d_in[2],
                          (const float*)d_in[3], (const float*)d_in[4] };
    float* out = (float*)d_out;

    // weight quantization (deterministic, recomputed every launch)
    for (int i = 0; i < 4; i++) {
        wabs_partial<<<1024, 256>>>(w[i], i);
        wabs_final<<<1, 256>>>(i);
        quant_w<<<4096, 256>>>(w[i], i);
    }
    rope_table<<<512, 256>>>();

    // QKV projections
    quant_act<<<NTOK, 256>>>(x, 0);
    gemm_i8<<<dim3(16, 32), 256>>>(0, nullptr, 0);   // q
    gemm_i8<<<dim3(16, 32), 256>>>(1, nullptr, 1);   // k
    gemm_i8<<<dim3(16, 32), 256>>>(2, nullptr, 2);   // v

    rope_apply<<<NTOK, 256>>>();

    // attention
    qk_gemm<<<dim3(16, 16, 32), 256>>>();
    softmax_kernel<<<BH * SEQ, 256>>>();
    pv_gemm<<<dim3(16, 32), 256>>>();

    // output projection
    quant_act<<<NTOK, 256>>>(nullptr, 1);
    gemm_i8<<<dim3(16, 32), 256>>>(3, out, 3);
}

// round 3
// speedup vs baseline: 1.7620x; 1.7620x over previous
#include <cuda_runtime.h>
#include <math.h>
#include <stdint.h>

#define HID 2048
#define NTOK 4096          // B*S = 2*2048
#define SEQ 2048
#define NH 16
#define HD 128
#define BH 32              // B*NH
static __device__ __constant__ float SCALE_ATTN = 0.08838834764831845f; // 1/sqrt(128)

// ---------------- scratch (device globals; no allocation allowed) ----------------
__device__ int8_t g_wq[4][HID * HID];            // ternary weights
__device__ float  g_ws[4];                       // weight scales
__device__ double g_wred[4 * 1024];              // partial |w| sums
__device__ int8_t g_xq[NTOK * HID];              // int8 activations
__device__ float  g_gs[NTOK];                    // per-token absmax scale g (incl. +EPS)
__device__ float  g_q[NTOK * HID];
__device__ float  g_k[NTOK * HID];
__device__ float  g_v[NTOK * HID];
__device__ float  g_ctx[NTOK * HID];
__device__ float  g_cos[SEQ * 64];
__device__ float  g_sin[SEQ * 64];
__device__ float  g_scores[(size_t)BH * SEQ * SEQ];  // 512 MB

// ---------------- PTX helpers ----------------
__device__ __forceinline__ uint32_t smaddr(const void* p) {
    return (uint32_t)__cvta_generic_to_shared(p);
}
__device__ __forceinline__ void cp16(uint32_t s, const void* g) {
    asm volatile("cp.async.cg.shared.global [%0], [%1], 16;\n" :: "r"(s), "l"(g));
}
#define CP_COMMIT() asm volatile("cp.async.commit_group;\n" ::)
#define CP_WAIT0()  asm volatile("cp.async.wait_group 0;\n" ::)

__device__ __forceinline__ void ldsm4(uint32_t& r0, uint32_t& r1, uint32_t& r2, uint32_t& r3, uint32_t a) {
    asm volatile("ldmatrix.sync.aligned.m8n8.x4.shared.b16 {%0,%1,%2,%3}, [%4];"
                 : "=r"(r0), "=r"(r1), "=r"(r2), "=r"(r3) : "r"(a));
}
__device__ __forceinline__ void mma_s8(int* c, uint32_t a0, uint32_t a1, uint32_t a2, uint32_t a3,
                                       uint32_t b0, uint32_t b1) {
    asm volatile("mma.sync.aligned.m16n8k32.row.col.s32.s8.s8.s32 "
                 "{%0,%1,%2,%3},{%4,%5,%6,%7},{%8,%9},{%0,%1,%2,%3};"
                 : "+r"(c[0]), "+r"(c[1]), "+r"(c[2]), "+r"(c[3])
                 : "r"(a0), "r"(a1), "r"(a2), "r"(a3), "r"(b0), "r"(b1));
}
__device__ __forceinline__ void mma_tf32(float* c, const float* a, float b0, float b1) {
    asm volatile("mma.sync.aligned.m16n8k8.row.col.f32.tf32.tf32.f32 "
                 "{%0,%1,%2,%3},{%4,%5,%6,%7},{%8,%9},{%0,%1,%2,%3};"
                 : "+f"(c[0]), "+f"(c[1]), "+f"(c[2]), "+f"(c[3])
                 : "r"(__float_as_uint(a[0])), "r"(__float_as_uint(a[1])),
                   "r"(__float_as_uint(a[2])), "r"(__float_as_uint(a[3])),
                   "r"(__float_as_uint(b0)), "r"(__float_as_uint(b1)));
}
__device__ __forceinline__ float tf32r(float x) {
    uint32_t u; asm("cvt.rna.tf32.f32 %0, %1;" : "=r"(u) : "f"(x));
    return __uint_as_float(u);
}
// split x = hi + lo, both tf32-representable; hi*hi + hi*lo + lo*hi ~= fp32 product
__device__ __forceinline__ void tf32split(float x, float& hi, float& lo) {
    hi = tf32r(x);
    lo = tf32r(x - hi);
}

// ---------------- weight scale: deterministic two-pass mean(|w|), 4 weights fused ----------------
__global__ __launch_bounds__(256) void wabs_partial_all(const float* __restrict__ w0, const float* __restrict__ w1,
                                                        const float* __restrict__ w2, const float* __restrict__ w3) {
    __shared__ double sh[256];
    int which = blockIdx.x >> 10, blk = blockIdx.x & 1023;
    const float* w = which == 0 ? w0 : which == 1 ? w1 : which == 2 ? w2 : w3;
    int base = blk * 4096;
    double acc = 0.0;
    for (int i = threadIdx.x; i < 4096; i += 256) acc += (double)fabsf(w[base + i]);
    sh[threadIdx.x] = acc; __syncthreads();
    for (int st = 128; st > 0; st >>= 1) {
        if (threadIdx.x < st) sh[threadIdx.x] += sh[threadIdx.x + st];
        __syncthreads();
    }
    if (threadIdx.x == 0) g_wred[which * 1024 + blk] = sh[0];
}

__global__ __launch_bounds__(256) void wabs_final_all() {
    __shared__ double sh[256];
    int which = blockIdx.x;
    double acc = 0.0;
    for (int i = threadIdx.x; i < 1024; i += 256) acc += g_wred[which * 1024 + i];
    sh[threadIdx.x] = acc; __syncthreads();
    for (int st = 128; st > 0; st >>= 1) {
        if (threadIdx.x < st) sh[threadIdx.x] += sh[threadIdx.x + st];
        __syncthreads();
    }
    if (threadIdx.x == 0)
        g_ws[which] = (float)(sh[0] / (double)(HID * HID)) + 1e-5f;
}

__global__ __launch_bounds__(256) void quant_w_all(const float* __restrict__ w0, const float* __restrict__ w1,
                                                   const float* __restrict__ w2, const float* __restrict__ w3) {
    int which = blockIdx.x >> 12, blk = blockIdx.x & 4095;
    const float* w = which == 0 ? w0 : which == 1 ? w1 : which == 2 ? w2 : w3;
    float s = g_ws[which];
    int base = blk * 1024;
    #pragma unroll
    for (int k = 0; k < 4; k++) {
        int i = base + threadIdx.x + k * 256;
        float t = rintf(w[i] / s);
        t = fminf(fmaxf(t, -1.0f), 1.0f);
        g_wq[which][i] = (int8_t)t;
    }
}

// ---------------- activation quant: per-token absmax int8 ----------------
__global__ __launch_bounds__(256) void quant_act(const float* __restrict__ xin, int use_ctx) {
    __shared__ float sh[256];
    int t = blockIdx.x;
    const float* x = use_ctx ? (const float*)g_ctx : xin;
    const float* row = x + (size_t)t * HID;
    float m = 0.0f;
    for (int i = threadIdx.x; i < HID; i += 256) m = fmaxf(m, fabsf(row[i]));
    sh[threadIdx.x] = m; __syncthreads();
    for (int st = 128; st > 0; st >>= 1) {
        if (threadIdx.x < st) sh[threadIdx.x] = fmaxf(sh[threadIdx.x], sh[threadIdx.x + st]);
        __syncthreads();
    }
    float g = sh[0] + 1e-5f;
    if (threadIdx.x == 0) g_gs[t] = g;
    float inv = 127.0f / g;
    for (int i = threadIdx.x; i < HID; i += 256) {
        float v = rintf(row[i] * inv);
        v = fminf(fmaxf(v, -127.0f), 127.0f);
        g_xq[(size_t)t * HID + i] = (int8_t)v;
    }
}

// ---------------- int8 IMMA GEMM: out[t,o] = (g_t*s/127) * sum_k xq*wq (bit-exact) ----------------
__global__ __launch_bounds__(256) void gemm_i8_mma(int which, float* __restrict__ out_param, int dest) {
    __shared__ int8_t As[2][128 * 80];
    __shared__ int8_t Bs[2][128 * 80];
    const int8_t* A = g_xq;
    const int8_t* B = g_wq[which];
    float* out = (dest == 0) ? g_q : (dest == 1) ? g_k : (dest == 2) ? g_v : out_param;

    int row0 = blockIdx.y * 128, col0 = blockIdx.x * 128;
    int tid = threadIdx.x, lane = tid & 31, wid = tid >> 5;
    int wm = (wid & 3) * 32, wn = (wid >> 2) * 64;

    int acc[2][8][4];
    #pragma unroll
    for (int mt = 0; mt < 2; mt++)
        #pragma unroll
        for (int n8 = 0; n8 < 8; n8++)
            #pragma unroll
            for (int q = 0; q < 4; q++) acc[mt][n8][q] = 0;

    int lr = tid >> 2, lc = (tid & 3) * 16;

    auto load_chunk = [&](int it, int buf) {
        int k0 = it * 64;
        #pragma unroll
        for (int s = 0; s < 2; s++) {
            int rr = lr + s * 64;
            cp16(smaddr(&As[buf][rr * 80 + lc]), A + (size_t)(row0 + rr) * HID + k0 + lc);
            cp16(smaddr(&Bs[buf][rr * 80 + lc]), B + (size_t)(col0 + rr) * HID + k0 + lc);
        }
        CP_COMMIT();
    };

    load_chunk(0, 0);
    for (int it = 0; it < 32; ++it) {
        int buf = it & 1;
        CP_WAIT0();
        __syncthreads();
        if (it + 1 < 32) load_chunk(it + 1, buf ^ 1);
        #pragma unroll
        for (int kk = 0; kk < 2; ++kk) {
            uint32_t a[2][4];
            #pragma unroll
            for (int mt = 0; mt < 2; ++mt) {
                uint32_t ad = smaddr(&As[buf][(wm + mt * 16 + (lane & 15)) * 80 + kk * 32 + (lane >> 4) * 16]);
                ldsm4(a[mt][0], a[mt][1], a[mt][2], a[mt][3], ad);
            }
            #pragma unroll
            for (int nt = 0; nt < 4; ++nt) {
                uint32_t b0, b1, b2, b3;
                uint32_t bd = smaddr(&Bs[buf][(wn + nt * 16 + (lane & 7) + ((lane >> 4) << 3)) * 80
                                              + kk * 32 + (((lane >> 3) & 1) << 4)]);
                ldsm4(b0, b1, b2, b3, bd);
                #pragma unroll
                for (int mt = 0; mt < 2; ++mt) {
                    mma_s8(acc[mt][nt * 2],     a[mt][0], a[mt][1], a[mt][2], a[mt][3], b0, b1);
                    mma_s8(acc[mt][nt * 2 + 1], a[mt][0], a[mt][1], a[mt][2], a[mt][3], b2, b3);
                }
            }
        }
        __syncthreads();
    }

    float sv = g_ws[which] * (1.0f / 127.0f);
    #pragma unroll
    for (int mt = 0; mt < 2; ++mt) {
        int r1 = row0 + wm + mt * 16 + (lane >> 2);
        int r2 = r1 + 8;
        float m1 = g_gs[r1] * sv, m2 = g_gs[r2] * sv;
        #pragma unroll
        for (int n8 = 0; n8 < 8; ++n8) {
            int cc = col0 + wn + n8 * 8 + (lane & 3) * 2;
            out[(size_t)r1 * HID + cc]     = (float)acc[mt][n8][0] * m1;
            out[(size_t)r1 * HID + cc + 1] = (float)acc[mt][n8][1] * m1;
            out[(size_t)r2 * HID + cc]     = (float)acc[mt][n8][2] * m2;
            out[(size_t)r2 * HID + cc + 1] = (float)acc[mt][n8][3] * m2;
        }
    }
}

// ---------------- RoPE table + apply ----------------
__global__ __launch_bounds__(256) void rope_table() {
    int idx = blockIdx.x * 256 + threadIdx.x;     // 131072 = 2048*64
    int pos = idx >> 6, j = idx & 63;
    double f = (double)pos * exp(-(double)j * (log(10000.0) / 64.0));
    g_cos[idx] = (float)cos(f);
    g_sin[idx] = (float)sin(f);
}

__global__ __launch_bounds__(256) void rope_apply() {
    int t = blockIdx.x;                 // token 0..4095
    int pos = t & (SEQ - 1);
    float* q = g_q + (size_t)t * HID;
    float* k = g_k + (size_t)t * HID;
    for (int p = threadIdx.x; p < 1024; p += 256) {
        int h = p >> 6, j = p & 63;
        float c = g_cos[pos * 64 + j];
        float s = g_sin[pos * 64 + j];
        int f1 = h * 128 + j, f2 = f1 + 64;
        float a = q[f1], b = q[f2];
        q[f1] = a * c - b * s;
        q[f2] = b * c + a * s;
        float ak = k[f1], bk = k[f2];
        k[f1] = ak * c - bk * s;
        k[f2] = bk * c + ak * s;
    }
}

// ---------------- QK^T via 3xTF32 MMA: scores[bh][i][j] ----------------
__global__ __launch_bounds__(256) void qk_mma() {
    __shared__ float Qs[2][128 * 20];
    __shared__ float Ks[2][128 * 20];
    int bh = blockIdx.z, b = bh >> 4, h = bh & 15;
    const float* qb = g_q + (size_t)b * SEQ * HID + h * HD;
    const float* kb = g_k + (size_t)b * SEQ * HID + h * HD;
    int i0 = blockIdx.y * 128, j0 = blockIdx.x * 128;
    int tid = threadIdx.x, lane = tid & 31, wid = tid >> 5;
    int wm = (wid & 3) * 32, wn = (wid >> 2) * 64;

    float acc[2][8][4];
    #pragma unroll
    for (int mt = 0; mt < 2; mt++)
        #pragma unroll
        for (int n8 = 0; n8 < 8; n8++)
            #pragma unroll
            for (int q = 0; q < 4; q++) acc[mt][n8][q] = 0.0f;

    int lr = tid >> 2, lc = (tid & 3) * 4;

    auto load_chunk = [&](int it, int buf) {
        int d0 = it * 16;
        #pragma unroll
        for (int s = 0; s < 2; s++) {
            int rr = lr + s * 64;
            cp16(smaddr(&Qs[buf][rr * 20 + lc]), qb + (size_t)(i0 + rr) * HID + d0 + lc);
            cp16(smaddr(&Ks[buf][rr * 20 + lc]), kb + (size_t)(j0 + rr) * HID + d0 + lc);
        }
        CP_COMMIT();
    };

    load_chunk(0, 0);
    for (int it = 0; it < 8; ++it) {
        int buf = it & 1;
        CP_WAIT0();
        __syncthreads();
        if (it + 1 < 8) load_chunk(it + 1, buf ^ 1);
        #pragma unroll
        for (int kk = 0; kk < 2; ++kk) {
            float ah[2][4], al[2][4];
            #pragma unroll
            for (int mt = 0; mt < 2; ++mt) {
                int base = (wm + mt * 16 + (lane >> 2)) * 20 + kk * 8 + (lane & 3);
                tf32split(Qs[buf][base],              ah[mt][0], al[mt][0]);
                tf32split(Qs[buf][base + 8 * 20],     ah[mt][1], al[mt][1]);
                tf32split(Qs[buf][base + 4],          ah[mt][2], al[mt][2]);
                tf32split(Qs[buf][base + 8 * 20 + 4], ah[mt][3], al[mt][3]);
            }
            #pragma unroll
            for (int nt = 0; nt < 8; ++nt) {
                int nb = (wn + nt * 8 + (lane >> 2)) * 20 + kk * 8 + (lane & 3);
                float bh0, bl0, bh1, bl1;
                tf32split(Ks[buf][nb],     bh0, bl0);
                tf32split(Ks[buf][nb + 4], bh1, bl1);
                #pragma unroll
                for (int mt = 0; mt < 2; ++mt) {
                    mma_tf32(acc[mt][nt], ah[mt], bh0, bh1);
                    mma_tf32(acc[mt][nt], al[mt], bh0, bh1);
                    mma_tf32(acc[mt][nt], ah[mt], bl0, bl1);
                }
            }
        }
        __syncthreads();
    }

    #pragma unroll
    for (int mt = 0; mt < 2; ++mt) {
        int r1 = i0 + wm + mt * 16 + (lane >> 2);
        #pragma unroll
        for (int n8 = 0; n8 < 8; ++n8) {
            int cc = j0 + wn + n8 * 8 + (lane & 3) * 2;
            size_t base1 = ((size_t)bh * SEQ + r1) * SEQ + cc;
            size_t base2 = ((size_t)bh * SEQ + r1 + 8) * SEQ + cc;
            g_scores[base1]     = acc[mt][n8][0] * SCALE_ATTN;
            g_scores[base1 + 1] = acc[mt][n8][1] * SCALE_ATTN;
            g_scores[base2]     = acc[mt][n8][2] * SCALE_ATTN;
            g_scores[base2 + 1] = acc[mt][n8][3] * SCALE_ATTN;
        }
    }
}

// ---------------- row softmax over 2048 ----------------
__global__ __launch_bounds__(256) void softmax_kernel() {
    __shared__ float sh[256];
    size_t row = blockIdx.x;
    float* p = g_scores + row * SEQ;
    int tid = threadIdx.x;
    float v[8];
    float m = -INFINITY;
    #pragma unroll
    for (int i = 0; i < 8; i++) { v[i] = p[tid + i * 256]; m = fmaxf(m, v[i]); }
    sh[tid] = m; __syncthreads();
    for (int st = 128; st > 0; st >>= 1) {
        if (tid < st) sh[tid] = fmaxf(sh[tid], sh[tid + st]);
        __syncthreads();
    }
    m = sh[0]; __syncthreads();
    float s = 0.0f;
    #pragma unroll
    for (int i = 0; i < 8; i++) { v[i] = expf(v[i] - m); s += v[i]; }
    sh[tid] = s; __syncthreads();
    for (int st = 128; st > 0; st >>= 1) {
        if (tid < st) sh[tid] += sh[tid + st];
        __syncthreads();
    }
    float inv = 1.0f / sh[0];
    #pragma unroll
    for (int i = 0; i < 8; i++) p[tid + i * 256] = v[i] * inv;
}

// ---------------- P*V via 3xTF32 MMA: ctx[b, i, h*128+d] ----------------
__global__ __launch_bounds__(256) void pv_mma() {
    __shared__ float Ps[2][128 * 20];
    __shared__ float Vs[2][16 * 136];
    int bh = blockIdx.y, b = bh >> 4, h = bh & 15;
    const float* vb = g_v + (size_t)b * SEQ * HID + h * HD;
    int i0 = blockIdx.x * 128;
    int tid = threadIdx.x, lane = tid & 31, wid = tid >> 5;
    int wm = (wid & 3) * 32, wn = (wid >> 2) * 64;

    float acc[2][8][4];
    #pragma unroll
    for (int mt = 0; mt < 2; mt++)
        #pragma unroll
        for (int n8 = 0; n8 < 8; n8++)
            #pragma unroll
            for (int q = 0; q < 4; q++) acc[mt][n8][q] = 0.0f;

    int lr = tid >> 2, lc = (tid & 3) * 4;       // P: rows 0..63, 4 float4/row
    int rv = tid >> 5, cv = (tid & 31) * 4;      // V: rows 0..7, 32 float4/row

    auto load_chunk = [&](int it, int buf) {
        int jc = it * 16;
        #pragma unroll
        for (int s = 0; s < 2; s++) {
            int rr = lr + s * 64;
            cp16(smaddr(&Ps[buf][rr * 20 + lc]),
                 &g_scores[((size_t)bh * SEQ + i0 + rr) * SEQ + jc + lc]);
            int rvv = rv + s * 8;
            cp16(smaddr(&Vs[buf][rvv * 136 + cv]), vb + (size_t)(jc + rvv) * HID + cv);
        }
        CP_COMMIT();
    };

    load_chunk(0, 0);
    for (int it = 0; it < 128; ++it) {
        int buf = it & 1;
        CP_WAIT0();
        __syncthreads();
        if (it + 1 < 128) load_chunk(it + 1, buf ^ 1);
        #pragma unroll
        for (int kk = 0; kk < 2; ++kk) {
            float ah[2][4], al[2][4];
            #pragma unroll
            for (int mt = 0; mt < 2; ++mt) {
                int base = (wm + mt * 16 + (lane >> 2)) * 20 + kk * 8 + (lane & 3);
                tf32split(Ps[buf][base],              ah[mt][0], al[mt][0]);
                tf32split(Ps[buf][base + 8 * 20],     ah[mt][1], al[mt][1]);
                tf32split(Ps[buf][base + 4],          ah[mt][2], al[mt][2]);
                tf32split(Ps[buf][base + 8 * 20 + 4], ah[mt][3], al[mt][3]);
            }
            #pragma unroll
            for (int nt = 0; nt < 8; ++nt) {
                int vbase = (kk * 8 + (lane & 3)) * 136 + wn + nt * 8 + (lane >> 2);
                float bh0, bl0, bh1, bl1;
                tf32split(Vs[buf][vbase],           bh0, bl0);
                tf32split(Vs[buf][vbase + 4 * 136], bh1, bl1);
                #pragma unroll
                for (int mt = 0; mt < 2; ++mt) {
                    mma_tf32(acc[mt][nt], ah[mt], bh0, bh1);
                    mma_tf32(acc[mt][nt], al[mt], bh0, bh1);
                    mma_tf32(acc[mt][nt], ah[mt], bl0, bl1);
                }
            }
        }
        __syncthreads();
    }

    #pragma unroll
    for (int mt = 0; mt < 2; ++mt) {
        int r1 = i0 + wm + mt * 16 + (lane >> 2);
        #pragma unroll
        for (int n8 = 0; n8 < 8; ++n8) {
            int dd = wn + n8 * 8 + (lane & 3) * 2;
            size_t base1 = (size_t)(b * SEQ + r1) * HID + h * HD + dd;
            size_t base2 = (size_t)(b * SEQ + r1 + 8) * HID + h * HD + dd;
            g_ctx[base1]     = acc[mt][n8][0];
            g_ctx[base1 + 1] = acc[mt][n8][1];
            g_ctx[base2]     = acc[mt][n8][2];
            g_ctx[base2 + 1] = acc[mt][n8][3];
        }
    }
}

// ---------------- launcher ----------------
extern "C" void kernel_launch(void* const* d_in, const int* in_sizes, int n_in,
                              void* d_out, int out_size) {
    const float* x = (const float*)d_in[0];
    const float* w0 = (const float*)d_in[1];
    const float* w1 = (const float*)d_in[2];
    const float* w2 = (const float*)d_in[3];
    const float* w3 = (const float*)d_in[4];
    float* out = (float*)d_out;

    // weight quantization (deterministic, recomputed every launch)
    wabs_partial_all<<<4096, 256>>>(w0, w1, w2, w3);
    wabs_final_all<<<4, 256>>>();
    quant_w_all<<<16384, 256>>>(w0, w1, w2, w3);
    rope_table<<<512, 256>>>();

    // QKV projections (exact int8 tensor-core GEMMs)
    quant_act<<<NTOK, 256>>>(x, 0);
    gemm_i8_mma<<<dim3(16, 32), 256>>>(0, nullptr, 0);   // q
    gemm_i8_mma<<<dim3(16, 32), 256>>>(1, nullptr, 1);   // k
    gemm_i8_mma<<<dim3(16, 32), 256>>>(2, nullptr, 2);   // v

    rope_apply<<<NTOK, 256>>>();

    // attention (3xTF32 tensor-core GEMMs, ~fp32 accuracy)
    qk_mma<<<dim3(16, 16, 32), 256>>>();
    softmax_kernel<<<BH * SEQ, 256>>>();
    pv_mma<<<dim3(16, 32), 256>>>();

    // output projection
    quant_act<<<NTOK, 256>>>(nullptr, 1);
    gemm_i8_mma<<<dim3(16, 32), 256>>>(3, out, 3);
}